// round 14
// baseline (speedup 1.0000x reference)
#include <cuda_runtime.h>
#include <cuda_fp16.h>
#include <cstdint>

#define NN   100000
#define NNP  100096   // 782 * 128 (padded M)
#define NE   1600000
#define DD   128
#define KK   512      // 3*D (relations) + D (self)
#define LL   3
#define NTILE 782
#define WT_ITEMS (LL * DD * KK)          // 196608
#define FH_ITEMS (NN * DD)               // 12800000

// ---------------- device scratch (static: no allocation allowed) ----------------
__device__ __half   g_agg16[(size_t)NNP * KK];   // [node][512] fp16: rel0|rel1|rel2|self
__device__ __half   g_h16[2][(size_t)NN * DD];   // ping-pong hidden states (fp16)
__device__ __half   g_hf16[(size_t)NN * DD];     // fp16(features) for layer 0
__device__ __half   g_bt16[LL][DD][KK];          // transposed fp16 weights: Bt[l][j][k]
__device__ int      g_deg[NN];
__device__ int      g_off[NN + 1];
__device__ int      g_cur[NN + 1];
__device__ unsigned g_csr[NE];                   // src | (etype<<20)
__device__ int      g_bsum[128];

// ---------------- small helpers ----------------
__device__ __forceinline__ uint32_t smem_u32(const void* p) {
    uint32_t a;
    asm("{ .reg .u64 t; cvta.to.shared.u64 t, %1; cvt.u32.u64 %0, t; }" : "=r"(a) : "l"(p));
    return a;
}

// ---------------- CSR construction (key = dst, etype packed in csr entry) -------
__global__ void k_hist(const int* __restrict__ dst) {
    int e = blockIdx.x * 256 + threadIdx.x;
    if (e < NE) atomicAdd(&g_deg[__ldg(&dst[e])], 1);
}
__global__ void k_scan1() {
    __shared__ int s[1024];
    int t = threadIdx.x;
    int i = blockIdx.x * 1024 + t;
    int v = (i < NN) ? g_deg[i] : 0;
    s[t] = v;
    __syncthreads();
    #pragma unroll
    for (int d = 1; d < 1024; d <<= 1) {
        int x = (t >= d) ? s[t - d] : 0;
        __syncthreads();
        s[t] += x;
        __syncthreads();
    }
    if (i < NN) g_off[i + 1] = s[t];
    if (t == 1023) g_bsum[blockIdx.x] = s[1023];
}
// scan3 with the block-sum scan fused in: every block redundantly scans g_bsum
__global__ void k_scan3() {
    __shared__ int s[128];
    int t = threadIdx.x;
    if (t < 128) s[t] = (t < 98) ? g_bsum[t] : 0;
    __syncthreads();
    #pragma unroll
    for (int d = 1; d < 128; d <<= 1) {
        int x = (t >= d && t < 128) ? s[t - d] : 0;
        __syncthreads();
        if (t < 128) s[t] += x;
        __syncthreads();
    }
    int off = (blockIdx.x == 0) ? 0 : s[blockIdx.x - 1];   // exclusive prefix
    int i = blockIdx.x * 1024 + t;
    if (i < NN) {
        int v = g_off[i + 1] + off;
        g_off[i + 1] = v;
        g_cur[i + 1] = v;
    }
    if (i == 0) { g_off[0] = 0; g_cur[0] = 0; }
}
__global__ void k_scatter(const int* __restrict__ src, const int* __restrict__ dst,
                          const int* __restrict__ ety) {
    int e = blockIdx.x * 256 + threadIdx.x;
    if (e < NE) {
        int d = __ldg(&dst[e]);
        int pos = atomicAdd(&g_cur[d], 1);
        g_csr[pos] = (unsigned)__ldg(&src[e]) | ((unsigned)__ldg(&ety[e]) << 20);
    }
}

// ---------------- weight transpose + feature copy -> fp16 (merged) --------------
__global__ void k_wtfh(const float* __restrict__ W, const float* __restrict__ Ws,
                       const float* __restrict__ feat) {
    size_t idx = (size_t)blockIdx.x * 256 + threadIdx.x;
    if (idx < WT_ITEMS) {
        int l = (int)(idx / (DD * KK));
        int rem = (int)(idx % (DD * KK));
        int j = rem / KK;
        int k = rem % KK;
        float v = (k < 384)
            ? W[(((size_t)l * 3 + (k >> 7)) * DD + (k & 127)) * DD + j]
            : Ws[((size_t)l * DD + (k - 384)) * DD + j];
        (&g_bt16[0][0][0])[idx] = __float2half_rn(v);
    } else if (idx < WT_ITEMS + (size_t)FH_ITEMS) {
        size_t i = idx - WT_ITEMS;
        g_hf16[i] = __float2half_rn(feat[i]);
    }
}

// ---------------- per-relation aggregation (one warp per node, fp16 h) ----------
// Warp-wide uint2 loads, warp-uniform relation branches, MLP-8 main loop.
__global__ void __launch_bounds__(256) k_agg(const uint2* __restrict__ h2) {
    int gw = (blockIdx.x * blockDim.x + threadIdx.x) >> 5;
    int lane = threadIdx.x & 31;
    if (gw >= NN) return;
    int e0 = g_off[gw], e1 = g_off[gw + 1];
    float4 a0 = {0, 0, 0, 0}, a1 = {0, 0, 0, 0}, a2 = {0, 0, 0, 0};

    auto acc = [&](unsigned t, uint2 v) {
        float2 f0 = __half22float2(*reinterpret_cast<__half2*>(&v.x));
        float2 f1 = __half22float2(*reinterpret_cast<__half2*>(&v.y));
        if (t == 0)      { a0.x += f0.x; a0.y += f0.y; a0.z += f1.x; a0.w += f1.y; }
        else if (t == 1) { a1.x += f0.x; a1.y += f0.y; a1.z += f1.x; a1.w += f1.y; }
        else             { a2.x += f0.x; a2.y += f0.y; a2.z += f1.x; a2.w += f1.y; }
    };

    int e = e0;
    for (; e + 7 < e1; e += 8) {          // MLP 8 per warp
        unsigned p[8];
        uint2 v[8];
        #pragma unroll
        for (int i = 0; i < 8; i++) p[i] = __ldcs(&g_csr[e + i]);
        #pragma unroll
        for (int i = 0; i < 8; i++)
            v[i] = __ldg(&h2[(size_t)(p[i] & 0xFFFFFu) * 32 + lane]);
        #pragma unroll
        for (int i = 0; i < 8; i++) acc(p[i] >> 20, v[i]);
    }
    for (; e + 3 < e1; e += 4) {          // MLP 4
        unsigned p0 = __ldcs(&g_csr[e]);
        unsigned p1 = __ldcs(&g_csr[e + 1]);
        unsigned p2 = __ldcs(&g_csr[e + 2]);
        unsigned p3 = __ldcs(&g_csr[e + 3]);
        uint2 v0 = __ldg(&h2[(size_t)(p0 & 0xFFFFFu) * 32 + lane]);
        uint2 v1 = __ldg(&h2[(size_t)(p1 & 0xFFFFFu) * 32 + lane]);
        uint2 v2 = __ldg(&h2[(size_t)(p2 & 0xFFFFFu) * 32 + lane]);
        uint2 v3 = __ldg(&h2[(size_t)(p3 & 0xFFFFFu) * 32 + lane]);
        acc(p0 >> 20, v0);
        acc(p1 >> 20, v1);
        acc(p2 >> 20, v2);
        acc(p3 >> 20, v3);
    }
    for (; e < e1; e++) {
        unsigned p0 = __ldcs(&g_csr[e]);
        uint2 v0 = __ldg(&h2[(size_t)(p0 & 0xFFFFFu) * 32 + lane]);
        acc(p0 >> 20, v0);
    }

    uint2 s3 = __ldg(&h2[(size_t)gw * 32 + lane]);   // self row, already fp16

    auto pack = [](const float4& v) {
        __half2 p0 = __floats2half2_rn(v.x, v.y);
        __half2 p1 = __floats2half2_rn(v.z, v.w);
        float2 o;
        o.x = __uint_as_float(*reinterpret_cast<uint32_t*>(&p0));
        o.y = __uint_as_float(*reinterpret_cast<uint32_t*>(&p1));
        return o;
    };
    // evict-normal stores: g_agg16 (102MB) + h (25MB) fit L2 -> gemm A reads hit L2
    float2* o = reinterpret_cast<float2*>(g_agg16) + (size_t)gw * 128;
    o[lane]      = pack(a0);
    o[32 + lane] = pack(a1);
    o[64 + lane] = pack(a2);
    float2 sf;
    sf.x = __uint_as_float(s3.x);
    sf.y = __uint_as_float(s3.y);
    o[96 + lane] = sf;
}

// ---------------- mma.sync fp16 GEMM: [NNP x 512] @ Bt[l]^T -> [NNP x 128] ------
// CTA tile 128x128, K=512 in 16 chunks of 32. 8 warps: 4(m) x 2(n), warp tile 32x64.
// m16n8k16 f16 mma, fp32 accumulate. 3-stage cp.async ring, one barrier per chunk.
static constexpr int GM_STAGES = 3;
static constexpr int RPH       = 40;                 // row pad in halves (32 + 8)
static constexpr int TILE_H    = 128 * RPH;          // halves per operand per stage
static constexpr int STAGE_H   = 2 * TILE_H;         // A + B
static constexpr int GEMM_SMEM = GM_STAGES * STAGE_H * 2;   // 61440 bytes

__device__ __forceinline__ void mma_f16_16x8x16(float c[4],
                                                uint32_t a0, uint32_t a1, uint32_t a2, uint32_t a3,
                                                uint32_t b0, uint32_t b1) {
    asm volatile(
        "mma.sync.aligned.m16n8k16.row.col.f32.f16.f16.f32 "
        "{%0,%1,%2,%3}, {%4,%5,%6,%7}, {%8,%9}, {%0,%1,%2,%3};"
        : "+f"(c[0]), "+f"(c[1]), "+f"(c[2]), "+f"(c[3])
        : "r"(a0), "r"(a1), "r"(a2), "r"(a3), "r"(b0), "r"(b1));
}

__global__ void __launch_bounds__(256, 2)
k_gemm(int layer, const float* __restrict__ bias,
       __half* __restrict__ hout16, float* __restrict__ hout32, int final_layer) {
    extern __shared__ __half smh[];
    uint32_t smaddr = smem_u32(smh);

    int tid = threadIdx.x, wid = tid >> 5, lane = tid & 31;
    int warp_m = wid >> 1, warp_n = wid & 1;
    int g = lane >> 2, q = lane & 3;

    const __half* A = g_agg16;
    const __half* B = &g_bt16[layer][0][0];
    size_t row0 = (size_t)blockIdx.x * 128;

    uint64_t pol;
    asm volatile("createpolicy.fractional.L2::evict_first.b64 %0;" : "=l"(pol));

    int r_ld[2], c_ld[2];
    #pragma unroll
    for (int i = 0; i < 2; i++) {
        int u = tid + i * 256;
        r_ld[i] = u >> 2;
        c_ld[i] = u & 3;
    }

    auto load_chunk = [&](int kc) {
        int st = kc % GM_STAGES;
        uint32_t sA = smaddr + (uint32_t)(st * STAGE_H) * 2u;
        uint32_t sB = sA + (uint32_t)TILE_H * 2u;
        #pragma unroll
        for (int i = 0; i < 2; i++) {
            const __half* gsrc = A + (row0 + (size_t)r_ld[i]) * KK + kc * 32 + c_ld[i] * 8;
            uint32_t d = sA + (uint32_t)(r_ld[i] * RPH + c_ld[i] * 8) * 2u;
            asm volatile("cp.async.cg.shared.global.L2::cache_hint [%0], [%1], 16, %2;"
                         :: "r"(d), "l"(gsrc), "l"(pol));
        }
        #pragma unroll
        for (int i = 0; i < 2; i++) {
            const __half* gsrc = B + (size_t)r_ld[i] * KK + kc * 32 + c_ld[i] * 8;
            uint32_t d = sB + (uint32_t)(r_ld[i] * RPH + c_ld[i] * 8) * 2u;
            asm volatile("cp.async.cg.shared.global [%0], [%1], 16;" :: "r"(d), "l"(gsrc));
        }
        asm volatile("cp.async.commit_group;" ::: "memory");
    };

    float acc[2][8][4];
    #pragma unroll
    for (int mt = 0; mt < 2; mt++)
        #pragma unroll
        for (int nt = 0; nt < 8; nt++)
            #pragma unroll
            for (int v = 0; v < 4; v++) acc[mt][nt][v] = 0.0f;

    load_chunk(0);
    load_chunk(1);

    #pragma unroll
    for (int kc = 0; kc < 16; kc++) {
        if (kc < 14) asm volatile("cp.async.wait_group 1;" ::: "memory");
        else         asm volatile("cp.async.wait_group 0;" ::: "memory");
        __syncthreads();   // single barrier: all warps finished chunk kc-1's compute

        if (kc + 2 < 16) load_chunk(kc + 2);   // overwrites stage (kc-1)%3: safe

        int st = kc % GM_STAGES;
        const __half* tA = smh + st * STAGE_H;
        const __half* tB = tA + TILE_H;

        #pragma unroll
        for (int ks = 0; ks < 2; ks++) {      // two k16 steps per 32-wide chunk
            int k0 = ks * 16;
            uint32_t af[2][4];
            #pragma unroll
            for (int mt = 0; mt < 2; mt++) {
                int rb = warp_m * 32 + mt * 16;
                af[mt][0] = *reinterpret_cast<const uint32_t*>(tA + (rb + g)     * RPH + k0 + 2 * q);
                af[mt][1] = *reinterpret_cast<const uint32_t*>(tA + (rb + g + 8) * RPH + k0 + 2 * q);
                af[mt][2] = *reinterpret_cast<const uint32_t*>(tA + (rb + g)     * RPH + k0 + 2 * q + 8);
                af[mt][3] = *reinterpret_cast<const uint32_t*>(tA + (rb + g + 8) * RPH + k0 + 2 * q + 8);
            }
            #pragma unroll
            for (int nt = 0; nt < 8; nt++) {
                int nb = warp_n * 64 + nt * 8;
                uint32_t b0 = *reinterpret_cast<const uint32_t*>(tB + (nb + g) * RPH + k0 + 2 * q);
                uint32_t b1 = *reinterpret_cast<const uint32_t*>(tB + (nb + g) * RPH + k0 + 2 * q + 8);
                mma_f16_16x8x16(acc[0][nt], af[0][0], af[0][1], af[0][2], af[0][3], b0, b1);
                mma_f16_16x8x16(acc[1][nt], af[1][0], af[1][1], af[1][2], af[1][3], b0, b1);
            }
        }
    }

    // epilogue: fp32 bias add; intermediate layers store fp16 h, final stores fp32
    #pragma unroll
    for (int mt = 0; mt < 2; mt++) {
        size_t r0 = row0 + (size_t)(warp_m * 32 + mt * 16 + g);
        size_t r1 = r0 + 8;
        #pragma unroll
        for (int nt = 0; nt < 8; nt++) {
            int cb = warp_n * 64 + nt * 8 + q * 2;
            float bz0 = __ldg(&bias[cb]), bz1 = __ldg(&bias[cb + 1]);
            float v00 = acc[mt][nt][0] + bz0, v01 = acc[mt][nt][1] + bz1;
            float v10 = acc[mt][nt][2] + bz0, v11 = acc[mt][nt][3] + bz1;
            if (final_layer) {
                if (r0 < NN) {
                    hout32[r0 * DD + cb]     = v00;
                    hout32[r0 * DD + cb + 1] = v01;
                }
                if (r1 < NN) {
                    hout32[r1 * DD + cb]     = v10;
                    hout32[r1 * DD + cb + 1] = v11;
                }
            } else {
                if (r0 < NN)
                    *reinterpret_cast<__half2*>(hout16 + r0 * DD + cb) = __floats2half2_rn(v00, v01);
                if (r1 < NN)
                    *reinterpret_cast<__half2*>(hout16 + r1 * DD + cb) = __floats2half2_rn(v10, v11);
            }
        }
    }
}

// ---------------- launch ----------------
extern "C" void kernel_launch(void* const* d_in, const int* in_sizes, int n_in,
                              void* d_out, int out_size) {
    const float* feat = (const float*)d_in[0];
    const float* W    = (const float*)d_in[1];
    const float* Ws   = (const float*)d_in[2];
    const float* bias = (const float*)d_in[3];
    const int*   src  = (const int*)d_in[4];
    const int*   dst  = (const int*)d_in[5];
    const int*   ety  = (const int*)d_in[6];
    float*       out  = (float*)d_out;

    static int smem_set = 0;
    if (!smem_set) {
        cudaFuncSetAttribute(k_gemm, cudaFuncAttributeMaxDynamicSharedMemorySize, GEMM_SMEM);
        smem_set = 1;
    }

    void* hsym = nullptr;
    cudaGetSymbolAddress(&hsym, g_h16);
    __half* h0 = (__half*)hsym;
    __half* h1 = h0 + (size_t)NN * DD;
    void* hfsym = nullptr;
    cudaGetSymbolAddress(&hfsym, g_hf16);
    __half* hf = (__half*)hfsym;
    void* degsym = nullptr;
    cudaGetSymbolAddress(&degsym, g_deg);

    // CSR by dst (graph fixed across layers -> build once per launch)
    cudaMemsetAsync(degsym, 0, (size_t)NN * sizeof(int));
    k_hist<<<(NE + 255) / 256, 256>>>(dst);
    k_scan1<<<98, 1024>>>();
    k_scan3<<<98, 1024>>>();           // block-sum scan fused in
    k_scatter<<<(NE + 255) / 256, 256>>>(src, dst, ety);
    k_wtfh<<<(int)((WT_ITEMS + (size_t)FH_ITEMS + 255) / 256), 256>>>(W, Ws, feat);

    const __half* hin = hf;
    for (int l = 0; l < LL; l++) {
        k_agg<<<(NN * 32 + 255) / 256, 256>>>((const uint2*)hin);
        __half* ho16 = (l == 0) ? h0 : h1;
        k_gemm<<<NTILE, 256, GEMM_SMEM>>>(l, bias + l * DD, ho16, out, (l == 2) ? 1 : 0);
        hin = ho16;
    }
}

// round 15
// speedup vs baseline: 1.1162x; 1.1162x over previous
#include <cuda_runtime.h>
#include <cuda_fp16.h>
#include <cstdint>

#define NN   100000
#define NNP  100096   // 782 * 128 (padded M)
#define NE   1600000
#define DD   128
#define KK   512      // 3*D (relations) + D (self)
#define LL   3
#define NTILE 782
#define WT_ITEMS (LL * DD * KK)          // 196608
#define FH_ITEMS (NN * DD)               // 12800000

// ---------------- device scratch (static: no allocation allowed) ----------------
__device__ __half   g_agg16[(size_t)NNP * KK];   // [node][512] fp16: rel0|rel1|rel2|self
__device__ __half   g_h16[2][(size_t)NN * DD];   // ping-pong hidden states (fp16)
__device__ __half   g_hf16[(size_t)NN * DD];     // fp16(features) for layer 0
__device__ __half   g_bt16[LL][DD][KK];          // transposed fp16 weights: Bt[l][j][k]
__device__ int      g_deg[NN];
__device__ int      g_off[NN + 1];
__device__ int      g_cur[NN + 1];
__device__ unsigned g_csr[NE];                   // src | (etype<<20)
__device__ int      g_bsum[128];

// ---------------- small helpers ----------------
__device__ __forceinline__ uint32_t smem_u32(const void* p) {
    uint32_t a;
    asm("{ .reg .u64 t; cvta.to.shared.u64 t, %1; cvt.u32.u64 %0, t; }" : "=r"(a) : "l"(p));
    return a;
}

// ---------------- CSR construction (key = dst, etype packed in csr entry) -------
__global__ void k_hist(const int* __restrict__ dst) {
    int e = blockIdx.x * 256 + threadIdx.x;
    if (e < NE) atomicAdd(&g_deg[__ldg(&dst[e])], 1);
}
__global__ void k_scan1() {
    __shared__ int s[1024];
    int t = threadIdx.x;
    int i = blockIdx.x * 1024 + t;
    int v = (i < NN) ? g_deg[i] : 0;
    s[t] = v;
    __syncthreads();
    #pragma unroll
    for (int d = 1; d < 1024; d <<= 1) {
        int x = (t >= d) ? s[t - d] : 0;
        __syncthreads();
        s[t] += x;
        __syncthreads();
    }
    if (i < NN) g_off[i + 1] = s[t];
    if (t == 1023) g_bsum[blockIdx.x] = s[1023];
}
// scan3 with the block-sum scan fused in: every block redundantly scans g_bsum
__global__ void k_scan3() {
    __shared__ int s[128];
    int t = threadIdx.x;
    if (t < 128) s[t] = (t < 98) ? g_bsum[t] : 0;
    __syncthreads();
    #pragma unroll
    for (int d = 1; d < 128; d <<= 1) {
        int x = (t >= d && t < 128) ? s[t - d] : 0;
        __syncthreads();
        if (t < 128) s[t] += x;
        __syncthreads();
    }
    int off = (blockIdx.x == 0) ? 0 : s[blockIdx.x - 1];   // exclusive prefix
    int i = blockIdx.x * 1024 + t;
    if (i < NN) {
        int v = g_off[i + 1] + off;
        g_off[i + 1] = v;
        g_cur[i + 1] = v;
    }
    if (i == 0) { g_off[0] = 0; g_cur[0] = 0; }
}
__global__ void k_scatter(const int* __restrict__ src, const int* __restrict__ dst,
                          const int* __restrict__ ety) {
    int e = blockIdx.x * 256 + threadIdx.x;
    if (e < NE) {
        int d = __ldg(&dst[e]);
        int pos = atomicAdd(&g_cur[d], 1);
        g_csr[pos] = (unsigned)__ldg(&src[e]) | ((unsigned)__ldg(&ety[e]) << 20);
    }
}

// ---------------- weight transpose + feature copy -> fp16 (merged) --------------
__global__ void k_wtfh(const float* __restrict__ W, const float* __restrict__ Ws,
                       const float* __restrict__ feat) {
    size_t idx = (size_t)blockIdx.x * 256 + threadIdx.x;
    if (idx < WT_ITEMS) {
        int l = (int)(idx / (DD * KK));
        int rem = (int)(idx % (DD * KK));
        int j = rem / KK;
        int k = rem % KK;
        float v = (k < 384)
            ? W[(((size_t)l * 3 + (k >> 7)) * DD + (k & 127)) * DD + j]
            : Ws[((size_t)l * DD + (k - 384)) * DD + j];
        (&g_bt16[0][0][0])[idx] = __float2half_rn(v);
    } else if (idx < WT_ITEMS + (size_t)FH_ITEMS) {
        size_t i = idx - WT_ITEMS;
        g_hf16[i] = __float2half_rn(feat[i]);
    }
}

// ---------------- per-relation aggregation (one warp per node, fp16 h) ----------
// R13 version: warp-wide uint2 loads, warp-uniform relation branches, MLP-4,
// evict-first (__stcs) agg stores to protect h residency in L2.
__global__ void __launch_bounds__(256) k_agg(const uint2* __restrict__ h2) {
    int gw = (blockIdx.x * blockDim.x + threadIdx.x) >> 5;
    int lane = threadIdx.x & 31;
    if (gw >= NN) return;
    int e0 = g_off[gw], e1 = g_off[gw + 1];
    float4 a0 = {0, 0, 0, 0}, a1 = {0, 0, 0, 0}, a2 = {0, 0, 0, 0};

    auto acc = [&](unsigned t, uint2 v) {
        float2 f0 = __half22float2(*reinterpret_cast<__half2*>(&v.x));
        float2 f1 = __half22float2(*reinterpret_cast<__half2*>(&v.y));
        if (t == 0)      { a0.x += f0.x; a0.y += f0.y; a0.z += f1.x; a0.w += f1.y; }
        else if (t == 1) { a1.x += f0.x; a1.y += f0.y; a1.z += f1.x; a1.w += f1.y; }
        else             { a2.x += f0.x; a2.y += f0.y; a2.z += f1.x; a2.w += f1.y; }
    };

    int e = e0;
    for (; e + 3 < e1; e += 4) {          // unroll 4: MLP 4 per warp
        unsigned p0 = __ldcs(&g_csr[e]);
        unsigned p1 = __ldcs(&g_csr[e + 1]);
        unsigned p2 = __ldcs(&g_csr[e + 2]);
        unsigned p3 = __ldcs(&g_csr[e + 3]);
        uint2 v0 = __ldg(&h2[(size_t)(p0 & 0xFFFFFu) * 32 + lane]);
        uint2 v1 = __ldg(&h2[(size_t)(p1 & 0xFFFFFu) * 32 + lane]);
        uint2 v2 = __ldg(&h2[(size_t)(p2 & 0xFFFFFu) * 32 + lane]);
        uint2 v3 = __ldg(&h2[(size_t)(p3 & 0xFFFFFu) * 32 + lane]);
        acc(p0 >> 20, v0);
        acc(p1 >> 20, v1);
        acc(p2 >> 20, v2);
        acc(p3 >> 20, v3);
    }
    for (; e < e1; e++) {
        unsigned p0 = __ldcs(&g_csr[e]);
        uint2 v0 = __ldg(&h2[(size_t)(p0 & 0xFFFFFu) * 32 + lane]);
        acc(p0 >> 20, v0);
    }

    uint2 s3 = __ldg(&h2[(size_t)gw * 32 + lane]);   // self row, already fp16

    auto pack = [](const float4& v) {
        __half2 p0 = __floats2half2_rn(v.x, v.y);
        __half2 p1 = __floats2half2_rn(v.z, v.w);
        float2 o;
        o.x = __uint_as_float(*reinterpret_cast<uint32_t*>(&p0));
        o.y = __uint_as_float(*reinterpret_cast<uint32_t*>(&p1));
        return o;
    };
    // g_agg16 row = 512 halves = 128 uint2; slice r at uint2 [r*32, r*32+32)
    float2* o = reinterpret_cast<float2*>(g_agg16) + (size_t)gw * 128;
    __stcs(&o[lane],      pack(a0));
    __stcs(&o[32 + lane], pack(a1));
    __stcs(&o[64 + lane], pack(a2));
    float2 sf;
    sf.x = __uint_as_float(s3.x);
    sf.y = __uint_as_float(s3.y);
    __stcs(&o[96 + lane], sf);
}

// ---------------- mma.sync fp16 GEMM: [NNP x 512] @ Bt[l]^T -> [NNP x 128] ------
// CTA tile 128x128, K=512 in 16 chunks of 32. 8 warps: 4(m) x 2(n), warp tile 32x64.
// m16n8k16 f16 mma, fp32 accumulate. 3-stage cp.async ring, one barrier per chunk.
static constexpr int GM_STAGES = 3;
static constexpr int RPH       = 40;                 // row pad in halves (32 + 8)
static constexpr int TILE_H    = 128 * RPH;          // halves per operand per stage
static constexpr int STAGE_H   = 2 * TILE_H;         // A + B
static constexpr int GEMM_SMEM = GM_STAGES * STAGE_H * 2;   // 61440 bytes

__device__ __forceinline__ void mma_f16_16x8x16(float c[4],
                                                uint32_t a0, uint32_t a1, uint32_t a2, uint32_t a3,
                                                uint32_t b0, uint32_t b1) {
    asm volatile(
        "mma.sync.aligned.m16n8k16.row.col.f32.f16.f16.f32 "
        "{%0,%1,%2,%3}, {%4,%5,%6,%7}, {%8,%9}, {%0,%1,%2,%3};"
        : "+f"(c[0]), "+f"(c[1]), "+f"(c[2]), "+f"(c[3])
        : "r"(a0), "r"(a1), "r"(a2), "r"(a3), "r"(b0), "r"(b1));
}

__global__ void __launch_bounds__(256, 2)
k_gemm(int layer, const float* __restrict__ bias,
       __half* __restrict__ hout16, float* __restrict__ hout32, int final_layer) {
    extern __shared__ __half smh[];
    uint32_t smaddr = smem_u32(smh);

    int tid = threadIdx.x, wid = tid >> 5, lane = tid & 31;
    int warp_m = wid >> 1, warp_n = wid & 1;
    int g = lane >> 2, q = lane & 3;

    const __half* A = g_agg16;
    const __half* B = &g_bt16[layer][0][0];
    size_t row0 = (size_t)blockIdx.x * 128;

    uint64_t pol;
    asm volatile("createpolicy.fractional.L2::evict_first.b64 %0;" : "=l"(pol));

    int r_ld[2], c_ld[2];
    #pragma unroll
    for (int i = 0; i < 2; i++) {
        int u = tid + i * 256;
        r_ld[i] = u >> 2;
        c_ld[i] = u & 3;
    }

    auto load_chunk = [&](int kc) {
        int st = kc % GM_STAGES;
        uint32_t sA = smaddr + (uint32_t)(st * STAGE_H) * 2u;
        uint32_t sB = sA + (uint32_t)TILE_H * 2u;
        #pragma unroll
        for (int i = 0; i < 2; i++) {
            const __half* gsrc = A + (row0 + (size_t)r_ld[i]) * KK + kc * 32 + c_ld[i] * 8;
            uint32_t d = sA + (uint32_t)(r_ld[i] * RPH + c_ld[i] * 8) * 2u;
            asm volatile("cp.async.cg.shared.global.L2::cache_hint [%0], [%1], 16, %2;"
                         :: "r"(d), "l"(gsrc), "l"(pol));
        }
        #pragma unroll
        for (int i = 0; i < 2; i++) {
            const __half* gsrc = B + (size_t)r_ld[i] * KK + kc * 32 + c_ld[i] * 8;
            uint32_t d = sB + (uint32_t)(r_ld[i] * RPH + c_ld[i] * 8) * 2u;
            asm volatile("cp.async.cg.shared.global [%0], [%1], 16;" :: "r"(d), "l"(gsrc));
        }
        asm volatile("cp.async.commit_group;" ::: "memory");
    };

    float acc[2][8][4];
    #pragma unroll
    for (int mt = 0; mt < 2; mt++)
        #pragma unroll
        for (int nt = 0; nt < 8; nt++)
            #pragma unroll
            for (int v = 0; v < 4; v++) acc[mt][nt][v] = 0.0f;

    load_chunk(0);
    load_chunk(1);

    #pragma unroll
    for (int kc = 0; kc < 16; kc++) {
        if (kc < 14) asm volatile("cp.async.wait_group 1;" ::: "memory");
        else         asm volatile("cp.async.wait_group 0;" ::: "memory");
        __syncthreads();   // single barrier: all warps finished chunk kc-1's compute

        if (kc + 2 < 16) load_chunk(kc + 2);   // overwrites stage (kc-1)%3: safe

        int st = kc % GM_STAGES;
        const __half* tA = smh + st * STAGE_H;
        const __half* tB = tA + TILE_H;

        #pragma unroll
        for (int ks = 0; ks < 2; ks++) {      // two k16 steps per 32-wide chunk
            int k0 = ks * 16;
            uint32_t af[2][4];
            #pragma unroll
            for (int mt = 0; mt < 2; mt++) {
                int rb = warp_m * 32 + mt * 16;
                af[mt][0] = *reinterpret_cast<const uint32_t*>(tA + (rb + g)     * RPH + k0 + 2 * q);
                af[mt][1] = *reinterpret_cast<const uint32_t*>(tA + (rb + g + 8) * RPH + k0 + 2 * q);
                af[mt][2] = *reinterpret_cast<const uint32_t*>(tA + (rb + g)     * RPH + k0 + 2 * q + 8);
                af[mt][3] = *reinterpret_cast<const uint32_t*>(tA + (rb + g + 8) * RPH + k0 + 2 * q + 8);
            }
            #pragma unroll
            for (int nt = 0; nt < 8; nt++) {
                int nb = warp_n * 64 + nt * 8;
                uint32_t b0 = *reinterpret_cast<const uint32_t*>(tB + (nb + g) * RPH + k0 + 2 * q);
                uint32_t b1 = *reinterpret_cast<const uint32_t*>(tB + (nb + g) * RPH + k0 + 2 * q + 8);
                mma_f16_16x8x16(acc[0][nt], af[0][0], af[0][1], af[0][2], af[0][3], b0, b1);
                mma_f16_16x8x16(acc[1][nt], af[1][0], af[1][1], af[1][2], af[1][3], b0, b1);
            }
        }
    }

    // epilogue: fp32 bias add; intermediate layers store fp16 h, final stores fp32
    #pragma unroll
    for (int mt = 0; mt < 2; mt++) {
        size_t r0 = row0 + (size_t)(warp_m * 32 + mt * 16 + g);
        size_t r1 = r0 + 8;
        #pragma unroll
        for (int nt = 0; nt < 8; nt++) {
            int cb = warp_n * 64 + nt * 8 + q * 2;
            float bz0 = __ldg(&bias[cb]), bz1 = __ldg(&bias[cb + 1]);
            float v00 = acc[mt][nt][0] + bz0, v01 = acc[mt][nt][1] + bz1;
            float v10 = acc[mt][nt][2] + bz0, v11 = acc[mt][nt][3] + bz1;
            if (final_layer) {
                if (r0 < NN) {
                    hout32[r0 * DD + cb]     = v00;
                    hout32[r0 * DD + cb + 1] = v01;
                }
                if (r1 < NN) {
                    hout32[r1 * DD + cb]     = v10;
                    hout32[r1 * DD + cb + 1] = v11;
                }
            } else {
                if (r0 < NN)
                    *reinterpret_cast<__half2*>(hout16 + r0 * DD + cb) = __floats2half2_rn(v00, v01);
                if (r1 < NN)
                    *reinterpret_cast<__half2*>(hout16 + r1 * DD + cb) = __floats2half2_rn(v10, v11);
            }
        }
    }
}

// ---------------- launch ----------------
extern "C" void kernel_launch(void* const* d_in, const int* in_sizes, int n_in,
                              void* d_out, int out_size) {
    const float* feat = (const float*)d_in[0];
    const float* W    = (const float*)d_in[1];
    const float* Ws   = (const float*)d_in[2];
    const float* bias = (const float*)d_in[3];
    const int*   src  = (const int*)d_in[4];
    const int*   dst  = (const int*)d_in[5];
    const int*   ety  = (const int*)d_in[6];
    float*       out  = (float*)d_out;

    static int smem_set = 0;
    if (!smem_set) {
        cudaFuncSetAttribute(k_gemm, cudaFuncAttributeMaxDynamicSharedMemorySize, GEMM_SMEM);
        smem_set = 1;
    }

    void* hsym = nullptr;
    cudaGetSymbolAddress(&hsym, g_h16);
    __half* h0 = (__half*)hsym;
    __half* h1 = h0 + (size_t)NN * DD;
    void* hfsym = nullptr;
    cudaGetSymbolAddress(&hfsym, g_hf16);
    __half* hf = (__half*)hfsym;
    void* degsym = nullptr;
    cudaGetSymbolAddress(&degsym, g_deg);

    // CSR by dst (graph fixed across layers -> build once per launch)
    cudaMemsetAsync(degsym, 0, (size_t)NN * sizeof(int));
    k_hist<<<(NE + 255) / 256, 256>>>(dst);
    k_scan1<<<98, 1024>>>();
    k_scan3<<<98, 1024>>>();           // block-sum scan fused in
    k_scatter<<<(NE + 255) / 256, 256>>>(src, dst, ety);
    k_wtfh<<<(int)((WT_ITEMS + (size_t)FH_ITEMS + 255) / 256), 256>>>(W, Ws, feat);

    const __half* hin = hf;
    for (int l = 0; l < LL; l++) {
        k_agg<<<(NN * 32 + 255) / 256, 256>>>((const uint2*)hin);
        __half* ho16 = (l == 0) ? h0 : h1;
        k_gemm<<<NTILE, 256, GEMM_SMEM>>>(l, bias + l * DD, ho16, out, (l == 2) ? 1 : 0);
        hin = ho16;
    }
}

// round 16
// speedup vs baseline: 1.1595x; 1.0388x over previous
#include <cuda_runtime.h>
#include <cuda_fp16.h>
#include <cstdint>

#define NN   100000
#define NNP  100096   // 782 * 128 (padded M)
#define NE   1600000
#define DD   128
#define KK   512      // 3*D (relations) + D (self)
#define LL   3
#define NTILE 782
#define WT_ITEMS (LL * DD * KK)          // 196608
#define FH_ITEMS (NN * DD)               // 12800000

// ---------------- device scratch (static: no allocation allowed) ----------------
__device__ __half   g_agg16[(size_t)NNP * KK];   // [node][512] fp16: rel0|rel1|rel2|self
__device__ __half   g_h16[2][(size_t)NN * DD];   // ping-pong hidden states (fp16)
__device__ __half   g_hf16[(size_t)NN * DD];     // fp16(features) for layer 0
__device__ __half   g_bt16[LL][DD][KK];          // transposed fp16 weights: Bt[l][j][k]
__device__ int      g_deg[NN];
__device__ int      g_off[NN + 1];
__device__ int      g_cur[NN + 1];
__device__ unsigned g_csr[NE];                   // src | (etype<<20)
__device__ int      g_bsum[128];

// ---------------- small helpers ----------------
__device__ __forceinline__ uint32_t smem_u32(const void* p) {
    uint32_t a;
    asm("{ .reg .u64 t; cvta.to.shared.u64 t, %1; cvt.u32.u64 %0, t; }" : "=r"(a) : "l"(p));
    return a;
}

// ---------------- preamble: hist + weight transpose + feature copy (merged) -----
// One grid covers all three index ranges; hist atomics overlap the copy streams.
__global__ void k_pre(const float* __restrict__ W, const float* __restrict__ Ws,
                      const float* __restrict__ feat, const int* __restrict__ dst) {
    size_t idx = (size_t)blockIdx.x * 256 + threadIdx.x;
    if (idx < NE) atomicAdd(&g_deg[__ldg(&dst[idx])], 1);
    if (idx < WT_ITEMS) {
        int l = (int)(idx / (DD * KK));
        int rem = (int)(idx % (DD * KK));
        int j = rem / KK;
        int k = rem % KK;
        float v = (k < 384)
            ? W[(((size_t)l * 3 + (k >> 7)) * DD + (k & 127)) * DD + j]
            : Ws[((size_t)l * DD + (k - 384)) * DD + j];
        (&g_bt16[0][0][0])[idx] = __float2half_rn(v);
    } else if (idx < WT_ITEMS + (size_t)FH_ITEMS) {
        size_t i = idx - WT_ITEMS;
        g_hf16[i] = __float2half_rn(feat[i]);
    }
}

__global__ void k_scan1() {
    __shared__ int s[1024];
    int t = threadIdx.x;
    int i = blockIdx.x * 1024 + t;
    int v = (i < NN) ? g_deg[i] : 0;
    s[t] = v;
    __syncthreads();
    #pragma unroll
    for (int d = 1; d < 1024; d <<= 1) {
        int x = (t >= d) ? s[t - d] : 0;
        __syncthreads();
        s[t] += x;
        __syncthreads();
    }
    if (i < NN) g_off[i + 1] = s[t];
    if (t == 1023) g_bsum[blockIdx.x] = s[1023];
}
// scan3 with the block-sum scan fused in: every block redundantly scans g_bsum
__global__ void k_scan3() {
    __shared__ int s[128];
    int t = threadIdx.x;
    if (t < 128) s[t] = (t < 98) ? g_bsum[t] : 0;
    __syncthreads();
    #pragma unroll
    for (int d = 1; d < 128; d <<= 1) {
        int x = (t >= d && t < 128) ? s[t - d] : 0;
        __syncthreads();
        if (t < 128) s[t] += x;
        __syncthreads();
    }
    int off = (blockIdx.x == 0) ? 0 : s[blockIdx.x - 1];   // exclusive prefix
    int i = blockIdx.x * 1024 + t;
    if (i < NN) {
        int v = g_off[i + 1] + off;
        g_off[i + 1] = v;
        g_cur[i + 1] = v;
    }
    if (i == 0) { g_off[0] = 0; g_cur[0] = 0; }
}
__global__ void k_scatter(const int* __restrict__ src, const int* __restrict__ dst,
                          const int* __restrict__ ety) {
    int e = blockIdx.x * 256 + threadIdx.x;
    if (e < NE) {
        int d = __ldg(&dst[e]);
        int pos = atomicAdd(&g_cur[d], 1);
        g_csr[pos] = (unsigned)__ldg(&src[e]) | ((unsigned)__ldg(&ety[e]) << 20);
    }
}

// ---------------- per-relation aggregation (one warp per node, fp16 h) ----------
// Warp-wide uint2 loads, warp-uniform relation branches, MLP-4,
// evict-first (__stcs) agg stores to protect h residency in L2.
__global__ void __launch_bounds__(256) k_agg(const uint2* __restrict__ h2) {
    int gw = (blockIdx.x * blockDim.x + threadIdx.x) >> 5;
    int lane = threadIdx.x & 31;
    if (gw >= NN) return;
    int e0 = g_off[gw], e1 = g_off[gw + 1];
    float4 a0 = {0, 0, 0, 0}, a1 = {0, 0, 0, 0}, a2 = {0, 0, 0, 0};

    auto acc = [&](unsigned t, uint2 v) {
        float2 f0 = __half22float2(*reinterpret_cast<__half2*>(&v.x));
        float2 f1 = __half22float2(*reinterpret_cast<__half2*>(&v.y));
        if (t == 0)      { a0.x += f0.x; a0.y += f0.y; a0.z += f1.x; a0.w += f1.y; }
        else if (t == 1) { a1.x += f0.x; a1.y += f0.y; a1.z += f1.x; a1.w += f1.y; }
        else             { a2.x += f0.x; a2.y += f0.y; a2.z += f1.x; a2.w += f1.y; }
    };

    int e = e0;
    for (; e + 3 < e1; e += 4) {          // unroll 4: MLP 4 per warp
        unsigned p0 = __ldcs(&g_csr[e]);
        unsigned p1 = __ldcs(&g_csr[e + 1]);
        unsigned p2 = __ldcs(&g_csr[e + 2]);
        unsigned p3 = __ldcs(&g_csr[e + 3]);
        uint2 v0 = __ldg(&h2[(size_t)(p0 & 0xFFFFFu) * 32 + lane]);
        uint2 v1 = __ldg(&h2[(size_t)(p1 & 0xFFFFFu) * 32 + lane]);
        uint2 v2 = __ldg(&h2[(size_t)(p2 & 0xFFFFFu) * 32 + lane]);
        uint2 v3 = __ldg(&h2[(size_t)(p3 & 0xFFFFFu) * 32 + lane]);
        acc(p0 >> 20, v0);
        acc(p1 >> 20, v1);
        acc(p2 >> 20, v2);
        acc(p3 >> 20, v3);
    }
    for (; e < e1; e++) {
        unsigned p0 = __ldcs(&g_csr[e]);
        uint2 v0 = __ldg(&h2[(size_t)(p0 & 0xFFFFFu) * 32 + lane]);
        acc(p0 >> 20, v0);
    }

    uint2 s3 = __ldg(&h2[(size_t)gw * 32 + lane]);   // self row, already fp16

    auto pack = [](const float4& v) {
        __half2 p0 = __floats2half2_rn(v.x, v.y);
        __half2 p1 = __floats2half2_rn(v.z, v.w);
        float2 o;
        o.x = __uint_as_float(*reinterpret_cast<uint32_t*>(&p0));
        o.y = __uint_as_float(*reinterpret_cast<uint32_t*>(&p1));
        return o;
    };
    // g_agg16 row = 512 halves = 128 uint2; slice r at uint2 [r*32, r*32+32)
    float2* o = reinterpret_cast<float2*>(g_agg16) + (size_t)gw * 128;
    __stcs(&o[lane],      pack(a0));
    __stcs(&o[32 + lane], pack(a1));
    __stcs(&o[64 + lane], pack(a2));
    float2 sf;
    sf.x = __uint_as_float(s3.x);
    sf.y = __uint_as_float(s3.y);
    __stcs(&o[96 + lane], sf);
}

// ---------------- mma.sync fp16 GEMM: [NNP x 512] @ Bt[l]^T -> [NNP x 128] ------
// CTA tile 128x128, K=512 in 8 chunks of 64 halves (half the barriers of 32-wide).
// 8 warps: 4(m) x 2(n), warp tile 32x64. m16n8k16 f16 mma, fp32 accumulate.
// 3-stage cp.async ring, one barrier per chunk. smem 110.6KB -> 2 CTAs/SM.
static constexpr int GM_STAGES = 3;
static constexpr int NC        = 8;                  // K chunks of 64
static constexpr int RPH       = 72;                 // row pad in halves (64 + 8)
static constexpr int TILE_H    = 128 * RPH;          // halves per operand per stage
static constexpr int STAGE_H   = 2 * TILE_H;         // A + B
static constexpr int GEMM_SMEM = GM_STAGES * STAGE_H * 2;   // 110592 bytes

__device__ __forceinline__ void mma_f16_16x8x16(float c[4],
                                                uint32_t a0, uint32_t a1, uint32_t a2, uint32_t a3,
                                                uint32_t b0, uint32_t b1) {
    asm volatile(
        "mma.sync.aligned.m16n8k16.row.col.f32.f16.f16.f32 "
        "{%0,%1,%2,%3}, {%4,%5,%6,%7}, {%8,%9}, {%0,%1,%2,%3};"
        : "+f"(c[0]), "+f"(c[1]), "+f"(c[2]), "+f"(c[3])
        : "r"(a0), "r"(a1), "r"(a2), "r"(a3), "r"(b0), "r"(b1));
}

__global__ void __launch_bounds__(256, 2)
k_gemm(int layer, const float* __restrict__ bias,
       __half* __restrict__ hout16, float* __restrict__ hout32, int final_layer) {
    extern __shared__ __half smh[];
    uint32_t smaddr = smem_u32(smh);

    int tid = threadIdx.x, wid = tid >> 5, lane = tid & 31;
    int warp_m = wid >> 1, warp_n = wid & 1;
    int g = lane >> 2, q = lane & 3;

    const __half* A = g_agg16;
    const __half* B = &g_bt16[layer][0][0];
    size_t row0 = (size_t)blockIdx.x * 128;

    uint64_t pol;
    asm volatile("createpolicy.fractional.L2::evict_first.b64 %0;" : "=l"(pol));

    // per-thread load slots: chunk row = 64 halves = 128B = 8 x 16B segs
    int r_ld[4], c_ld[4];
    #pragma unroll
    for (int i = 0; i < 4; i++) {
        int u = tid + i * 256;
        r_ld[i] = u >> 3;
        c_ld[i] = u & 7;
    }

    auto load_chunk = [&](int kc) {
        int st = kc % GM_STAGES;
        uint32_t sA = smaddr + (uint32_t)(st * STAGE_H) * 2u;
        uint32_t sB = sA + (uint32_t)TILE_H * 2u;
        #pragma unroll
        for (int i = 0; i < 4; i++) {
            const __half* gsrc = A + (row0 + (size_t)r_ld[i]) * KK + kc * 64 + c_ld[i] * 8;
            uint32_t d = sA + (uint32_t)(r_ld[i] * RPH + c_ld[i] * 8) * 2u;
            asm volatile("cp.async.cg.shared.global.L2::cache_hint [%0], [%1], 16, %2;"
                         :: "r"(d), "l"(gsrc), "l"(pol));
        }
        #pragma unroll
        for (int i = 0; i < 4; i++) {
            const __half* gsrc = B + (size_t)r_ld[i] * KK + kc * 64 + c_ld[i] * 8;
            uint32_t d = sB + (uint32_t)(r_ld[i] * RPH + c_ld[i] * 8) * 2u;
            asm volatile("cp.async.cg.shared.global [%0], [%1], 16;" :: "r"(d), "l"(gsrc));
        }
        asm volatile("cp.async.commit_group;" ::: "memory");
    };

    float acc[2][8][4];
    #pragma unroll
    for (int mt = 0; mt < 2; mt++)
        #pragma unroll
        for (int nt = 0; nt < 8; nt++)
            #pragma unroll
            for (int v = 0; v < 4; v++) acc[mt][nt][v] = 0.0f;

    load_chunk(0);
    load_chunk(1);

    #pragma unroll
    for (int kc = 0; kc < NC; kc++) {
        if (kc < NC - 2) asm volatile("cp.async.wait_group 1;" ::: "memory");
        else             asm volatile("cp.async.wait_group 0;" ::: "memory");
        __syncthreads();   // single barrier: all warps finished chunk kc-1's compute

        if (kc + 2 < NC) load_chunk(kc + 2);   // overwrites stage (kc-1)%3: safe

        int st = kc % GM_STAGES;
        const __half* tA = smh + st * STAGE_H;
        const __half* tB = tA + TILE_H;

        #pragma unroll
        for (int ks = 0; ks < 4; ks++) {      // four k16 steps per 64-wide chunk
            int k0 = ks * 16;
            uint32_t af[2][4];
            #pragma unroll
            for (int mt = 0; mt < 2; mt++) {
                int rb = warp_m * 32 + mt * 16;
                af[mt][0] = *reinterpret_cast<const uint32_t*>(tA + (rb + g)     * RPH + k0 + 2 * q);
                af[mt][1] = *reinterpret_cast<const uint32_t*>(tA + (rb + g + 8) * RPH + k0 + 2 * q);
                af[mt][2] = *reinterpret_cast<const uint32_t*>(tA + (rb + g)     * RPH + k0 + 2 * q + 8);
                af[mt][3] = *reinterpret_cast<const uint32_t*>(tA + (rb + g + 8) * RPH + k0 + 2 * q + 8);
            }
            #pragma unroll
            for (int nt = 0; nt < 8; nt++) {
                int nb = warp_n * 64 + nt * 8;
                uint32_t b0 = *reinterpret_cast<const uint32_t*>(tB + (nb + g) * RPH + k0 + 2 * q);
                uint32_t b1 = *reinterpret_cast<const uint32_t*>(tB + (nb + g) * RPH + k0 + 2 * q + 8);
                mma_f16_16x8x16(acc[0][nt], af[0][0], af[0][1], af[0][2], af[0][3], b0, b1);
                mma_f16_16x8x16(acc[1][nt], af[1][0], af[1][1], af[1][2], af[1][3], b0, b1);
            }
        }
    }

    // epilogue: fp32 bias add; intermediate layers store fp16 h, final stores fp32
    #pragma unroll
    for (int mt = 0; mt < 2; mt++) {
        size_t r0 = row0 + (size_t)(warp_m * 32 + mt * 16 + g);
        size_t r1 = r0 + 8;
        #pragma unroll
        for (int nt = 0; nt < 8; nt++) {
            int cb = warp_n * 64 + nt * 8 + q * 2;
            float bz0 = __ldg(&bias[cb]), bz1 = __ldg(&bias[cb + 1]);
            float v00 = acc[mt][nt][0] + bz0, v01 = acc[mt][nt][1] + bz1;
            float v10 = acc[mt][nt][2] + bz0, v11 = acc[mt][nt][3] + bz1;
            if (final_layer) {
                if (r0 < NN) {
                    hout32[r0 * DD + cb]     = v00;
                    hout32[r0 * DD + cb + 1] = v01;
                }
                if (r1 < NN) {
                    hout32[r1 * DD + cb]     = v10;
                    hout32[r1 * DD + cb + 1] = v11;
                }
            } else {
                if (r0 < NN)
                    *reinterpret_cast<__half2*>(hout16 + r0 * DD + cb) = __floats2half2_rn(v00, v01);
                if (r1 < NN)
                    *reinterpret_cast<__half2*>(hout16 + r1 * DD + cb) = __floats2half2_rn(v10, v11);
            }
        }
    }
}

// ---------------- launch ----------------
extern "C" void kernel_launch(void* const* d_in, const int* in_sizes, int n_in,
                              void* d_out, int out_size) {
    const float* feat = (const float*)d_in[0];
    const float* W    = (const float*)d_in[1];
    const float* Ws   = (const float*)d_in[2];
    const float* bias = (const float*)d_in[3];
    const int*   src  = (const int*)d_in[4];
    const int*   dst  = (const int*)d_in[5];
    const int*   ety  = (const int*)d_in[6];
    float*       out  = (float*)d_out;

    static int smem_set = 0;
    if (!smem_set) {
        cudaFuncSetAttribute(k_gemm, cudaFuncAttributeMaxDynamicSharedMemorySize, GEMM_SMEM);
        smem_set = 1;
    }

    void* hsym = nullptr;
    cudaGetSymbolAddress(&hsym, g_h16);
    __half* h0 = (__half*)hsym;
    __half* h1 = h0 + (size_t)NN * DD;
    void* hfsym = nullptr;
    cudaGetSymbolAddress(&hfsym, g_hf16);
    __half* hf = (__half*)hfsym;
    void* degsym = nullptr;
    cudaGetSymbolAddress(&degsym, g_deg);

    // CSR by dst (graph fixed across layers -> build once per launch)
    cudaMemsetAsync(degsym, 0, (size_t)NN * sizeof(int));
    k_pre<<<(int)((WT_ITEMS + (size_t)FH_ITEMS + 255) / 256), 256>>>(W, Ws, feat, dst);
    k_scan1<<<98, 1024>>>();
    k_scan3<<<98, 1024>>>();           // block-sum scan fused in
    k_scatter<<<(NE + 255) / 256, 256>>>(src, dst, ety);

    const __half* hin = hf;
    for (int l = 0; l < LL; l++) {
        k_agg<<<(NN * 32 + 255) / 256, 256>>>((const uint2*)hin);
        __half* ho16 = (l == 0) ? h0 : h1;
        k_gemm<<<NTILE, 256, GEMM_SMEM>>>(l, bias + l * DD, ho16, out, (l == 2) ? 1 : 0);
        hin = ho16;
    }
}

// round 17
// speedup vs baseline: 1.1726x; 1.0113x over previous
#include <cuda_runtime.h>
#include <cuda_fp16.h>
#include <cstdint>

#define NN   100000
#define NNP  100096   // 782 * 128 (padded M)
#define NE   1600000
#define DD   128
#define KK   512      // 3*D (relations) + D (self)
#define LL   3
#define NTILE 782
#define WT_ITEMS (LL * DD * KK)          // 196608
#define FH_ITEMS (NN * DD)               // 12800000

// ---------------- device scratch (static: no allocation allowed) ----------------
__device__ __half   g_agg16[(size_t)NNP * KK];   // [node][512] fp16: rel0|rel1|rel2|self
__device__ __half   g_h16[2][(size_t)NN * DD];   // ping-pong hidden states (fp16)
__device__ __half   g_hf16[(size_t)NN * DD];     // fp16(features) for layer 0
__device__ __half   g_bt16[LL][DD][KK];          // transposed fp16 weights: Bt[l][j][k]
__device__ int      g_deg[NN];
__device__ int      g_off[NN + 1];
__device__ int      g_rank[NE];                  // per-edge rank within its dst segment
__device__ unsigned g_csr[NE];                   // src | (etype<<20)
__device__ int      g_bsum[128];

// ---------------- small helpers ----------------
__device__ __forceinline__ uint32_t smem_u32(const void* p) {
    uint32_t a;
    asm("{ .reg .u64 t; cvta.to.shared.u64 t, %1; cvt.u32.u64 %0, t; }" : "=r"(a) : "l"(p));
    return a;
}

// ---------------- preamble: hist(+rank) + weight transpose + feature copy -------
// One grid covers all index ranges; hist atomics overlap the copy streams.
// The atomic's return value IS the edge's rank within its dst segment.
__global__ void k_pre(const float* __restrict__ W, const float* __restrict__ Ws,
                      const float* __restrict__ feat, const int* __restrict__ dst) {
    size_t idx = (size_t)blockIdx.x * 256 + threadIdx.x;
    if (idx < NE) g_rank[idx] = atomicAdd(&g_deg[__ldg(&dst[idx])], 1);
    if (idx < WT_ITEMS) {
        int l = (int)(idx / (DD * KK));
        int rem = (int)(idx % (DD * KK));
        int j = rem / KK;
        int k = rem % KK;
        float v = (k < 384)
            ? W[(((size_t)l * 3 + (k >> 7)) * DD + (k & 127)) * DD + j]
            : Ws[((size_t)l * DD + (k - 384)) * DD + j];
        (&g_bt16[0][0][0])[idx] = __float2half_rn(v);
    } else if (idx < WT_ITEMS + (size_t)FH_ITEMS) {
        size_t i = idx - WT_ITEMS;
        g_hf16[i] = __float2half_rn(feat[i]);
    }
}

__global__ void k_scan1() {
    __shared__ int s[1024];
    int t = threadIdx.x;
    int i = blockIdx.x * 1024 + t;
    int v = (i < NN) ? g_deg[i] : 0;
    s[t] = v;
    __syncthreads();
    #pragma unroll
    for (int d = 1; d < 1024; d <<= 1) {
        int x = (t >= d) ? s[t - d] : 0;
        __syncthreads();
        s[t] += x;
        __syncthreads();
    }
    if (i < NN) g_off[i + 1] = s[t];
    if (t == 1023) g_bsum[blockIdx.x] = s[1023];
}
// scan3 with the block-sum scan fused in: every block redundantly scans g_bsum
__global__ void k_scan3() {
    __shared__ int s[128];
    int t = threadIdx.x;
    if (t < 128) s[t] = (t < 98) ? g_bsum[t] : 0;
    __syncthreads();
    #pragma unroll
    for (int d = 1; d < 128; d <<= 1) {
        int x = (t >= d && t < 128) ? s[t - d] : 0;
        __syncthreads();
        if (t < 128) s[t] += x;
        __syncthreads();
    }
    int off = (blockIdx.x == 0) ? 0 : s[blockIdx.x - 1];   // exclusive prefix
    int i = blockIdx.x * 1024 + t;
    if (i < NN) g_off[i + 1] += off;
    if (i == 0) g_off[0] = 0;
}
// atomic-free scatter: slot = off[dst] + rank (rank captured during hist)
__global__ void k_scatter(const int* __restrict__ src, const int* __restrict__ dst,
                          const int* __restrict__ ety) {
    int e = blockIdx.x * 256 + threadIdx.x;
    if (e < NE) {
        int pos = g_off[__ldg(&dst[e])] + g_rank[e];
        g_csr[pos] = (unsigned)__ldg(&src[e]) | ((unsigned)__ldg(&ety[e]) << 20);
    }
}

// ---------------- per-relation aggregation (one warp per node, fp16 h) ----------
// Warp-wide uint2 loads, warp-uniform relation branches, MLP-4,
// evict-first (__stcs) agg stores to protect h residency in L2.
__global__ void __launch_bounds__(256) k_agg(const uint2* __restrict__ h2) {
    int gw = (blockIdx.x * blockDim.x + threadIdx.x) >> 5;
    int lane = threadIdx.x & 31;
    if (gw >= NN) return;
    int e0 = g_off[gw], e1 = g_off[gw + 1];
    float4 a0 = {0, 0, 0, 0}, a1 = {0, 0, 0, 0}, a2 = {0, 0, 0, 0};

    auto acc = [&](unsigned t, uint2 v) {
        float2 f0 = __half22float2(*reinterpret_cast<__half2*>(&v.x));
        float2 f1 = __half22float2(*reinterpret_cast<__half2*>(&v.y));
        if (t == 0)      { a0.x += f0.x; a0.y += f0.y; a0.z += f1.x; a0.w += f1.y; }
        else if (t == 1) { a1.x += f0.x; a1.y += f0.y; a1.z += f1.x; a1.w += f1.y; }
        else             { a2.x += f0.x; a2.y += f0.y; a2.z += f1.x; a2.w += f1.y; }
    };

    int e = e0;
    for (; e + 3 < e1; e += 4) {          // unroll 4: MLP 4 per warp
        unsigned p0 = __ldcs(&g_csr[e]);
        unsigned p1 = __ldcs(&g_csr[e + 1]);
        unsigned p2 = __ldcs(&g_csr[e + 2]);
        unsigned p3 = __ldcs(&g_csr[e + 3]);
        uint2 v0 = __ldg(&h2[(size_t)(p0 & 0xFFFFFu) * 32 + lane]);
        uint2 v1 = __ldg(&h2[(size_t)(p1 & 0xFFFFFu) * 32 + lane]);
        uint2 v2 = __ldg(&h2[(size_t)(p2 & 0xFFFFFu) * 32 + lane]);
        uint2 v3 = __ldg(&h2[(size_t)(p3 & 0xFFFFFu) * 32 + lane]);
        acc(p0 >> 20, v0);
        acc(p1 >> 20, v1);
        acc(p2 >> 20, v2);
        acc(p3 >> 20, v3);
    }
    for (; e < e1; e++) {
        unsigned p0 = __ldcs(&g_csr[e]);
        uint2 v0 = __ldg(&h2[(size_t)(p0 & 0xFFFFFu) * 32 + lane]);
        acc(p0 >> 20, v0);
    }

    uint2 s3 = __ldg(&h2[(size_t)gw * 32 + lane]);   // self row, already fp16

    auto pack = [](const float4& v) {
        __half2 p0 = __floats2half2_rn(v.x, v.y);
        __half2 p1 = __floats2half2_rn(v.z, v.w);
        float2 o;
        o.x = __uint_as_float(*reinterpret_cast<uint32_t*>(&p0));
        o.y = __uint_as_float(*reinterpret_cast<uint32_t*>(&p1));
        return o;
    };
    // g_agg16 row = 512 halves = 128 uint2; slice r at uint2 [r*32, r*32+32)
    float2* o = reinterpret_cast<float2*>(g_agg16) + (size_t)gw * 128;
    __stcs(&o[lane],      pack(a0));
    __stcs(&o[32 + lane], pack(a1));
    __stcs(&o[64 + lane], pack(a2));
    float2 sf;
    sf.x = __uint_as_float(s3.x);
    sf.y = __uint_as_float(s3.y);
    __stcs(&o[96 + lane], sf);
}

// ---------------- mma.sync fp16 GEMM: [NNP x 512] @ Bt[l]^T -> [NNP x 128] ------
// CTA tile 128x128, K=512 in 8 chunks of 64 halves. 8 warps: 4(m) x 2(n),
// warp tile 32x64. m16n8k16 f16 mma, fp32 accumulate. 3-stage cp.async ring,
// one barrier per chunk. smem 110.6KB -> 2 CTAs/SM.
static constexpr int GM_STAGES = 3;
static constexpr int NC        = 8;                  // K chunks of 64
static constexpr int RPH       = 72;                 // row pad in halves (64 + 8)
static constexpr int TILE_H    = 128 * RPH;          // halves per operand per stage
static constexpr int STAGE_H   = 2 * TILE_H;         // A + B
static constexpr int GEMM_SMEM = GM_STAGES * STAGE_H * 2;   // 110592 bytes

__device__ __forceinline__ void mma_f16_16x8x16(float c[4],
                                                uint32_t a0, uint32_t a1, uint32_t a2, uint32_t a3,
                                                uint32_t b0, uint32_t b1) {
    asm volatile(
        "mma.sync.aligned.m16n8k16.row.col.f32.f16.f16.f32 "
        "{%0,%1,%2,%3}, {%4,%5,%6,%7}, {%8,%9}, {%0,%1,%2,%3};"
        : "+f"(c[0]), "+f"(c[1]), "+f"(c[2]), "+f"(c[3])
        : "r"(a0), "r"(a1), "r"(a2), "r"(a3), "r"(b0), "r"(b1));
}

__global__ void __launch_bounds__(256, 2)
k_gemm(int layer, const float* __restrict__ bias,
       __half* __restrict__ hout16, float* __restrict__ hout32, int final_layer) {
    extern __shared__ __half smh[];
    uint32_t smaddr = smem_u32(smh);

    int tid = threadIdx.x, wid = tid >> 5, lane = tid & 31;
    int warp_m = wid >> 1, warp_n = wid & 1;
    int g = lane >> 2, q = lane & 3;

    const __half* A = g_agg16;
    const __half* B = &g_bt16[layer][0][0];
    size_t row0 = (size_t)blockIdx.x * 128;

    uint64_t pol;
    asm volatile("createpolicy.fractional.L2::evict_first.b64 %0;" : "=l"(pol));

    // per-thread load slots: chunk row = 64 halves = 128B = 8 x 16B segs
    int r_ld[4], c_ld[4];
    #pragma unroll
    for (int i = 0; i < 4; i++) {
        int u = tid + i * 256;
        r_ld[i] = u >> 3;
        c_ld[i] = u & 7;
    }

    auto load_chunk = [&](int kc) {
        int st = kc % GM_STAGES;
        uint32_t sA = smaddr + (uint32_t)(st * STAGE_H) * 2u;
        uint32_t sB = sA + (uint32_t)TILE_H * 2u;
        #pragma unroll
        for (int i = 0; i < 4; i++) {
            const __half* gsrc = A + (row0 + (size_t)r_ld[i]) * KK + kc * 64 + c_ld[i] * 8;
            uint32_t d = sA + (uint32_t)(r_ld[i] * RPH + c_ld[i] * 8) * 2u;
            asm volatile("cp.async.cg.shared.global.L2::cache_hint [%0], [%1], 16, %2;"
                         :: "r"(d), "l"(gsrc), "l"(pol));
        }
        #pragma unroll
        for (int i = 0; i < 4; i++) {
            const __half* gsrc = B + (size_t)r_ld[i] * KK + kc * 64 + c_ld[i] * 8;
            uint32_t d = sB + (uint32_t)(r_ld[i] * RPH + c_ld[i] * 8) * 2u;
            asm volatile("cp.async.cg.shared.global [%0], [%1], 16;" :: "r"(d), "l"(gsrc));
        }
        asm volatile("cp.async.commit_group;" ::: "memory");
    };

    float acc[2][8][4];
    #pragma unroll
    for (int mt = 0; mt < 2; mt++)
        #pragma unroll
        for (int nt = 0; nt < 8; nt++)
            #pragma unroll
            for (int v = 0; v < 4; v++) acc[mt][nt][v] = 0.0f;

    load_chunk(0);
    load_chunk(1);

    #pragma unroll
    for (int kc = 0; kc < NC; kc++) {
        if (kc < NC - 2) asm volatile("cp.async.wait_group 1;" ::: "memory");
        else             asm volatile("cp.async.wait_group 0;" ::: "memory");
        __syncthreads();   // single barrier: all warps finished chunk kc-1's compute

        if (kc + 2 < NC) load_chunk(kc + 2);   // overwrites stage (kc-1)%3: safe

        int st = kc % GM_STAGES;
        const __half* tA = smh + st * STAGE_H;
        const __half* tB = tA + TILE_H;

        #pragma unroll
        for (int ks = 0; ks < 4; ks++) {      // four k16 steps per 64-wide chunk
            int k0 = ks * 16;
            uint32_t af[2][4];
            #pragma unroll
            for (int mt = 0; mt < 2; mt++) {
                int rb = warp_m * 32 + mt * 16;
                af[mt][0] = *reinterpret_cast<const uint32_t*>(tA + (rb + g)     * RPH + k0 + 2 * q);
                af[mt][1] = *reinterpret_cast<const uint32_t*>(tA + (rb + g + 8) * RPH + k0 + 2 * q);
                af[mt][2] = *reinterpret_cast<const uint32_t*>(tA + (rb + g)     * RPH + k0 + 2 * q + 8);
                af[mt][3] = *reinterpret_cast<const uint32_t*>(tA + (rb + g + 8) * RPH + k0 + 2 * q + 8);
            }
            #pragma unroll
            for (int nt = 0; nt < 8; nt++) {
                int nb = warp_n * 64 + nt * 8;
                uint32_t b0 = *reinterpret_cast<const uint32_t*>(tB + (nb + g) * RPH + k0 + 2 * q);
                uint32_t b1 = *reinterpret_cast<const uint32_t*>(tB + (nb + g) * RPH + k0 + 2 * q + 8);
                mma_f16_16x8x16(acc[0][nt], af[0][0], af[0][1], af[0][2], af[0][3], b0, b1);
                mma_f16_16x8x16(acc[1][nt], af[1][0], af[1][1], af[1][2], af[1][3], b0, b1);
            }
        }
    }

    // epilogue: fp32 bias add; intermediate layers store fp16 h, final stores fp32
    #pragma unroll
    for (int mt = 0; mt < 2; mt++) {
        size_t r0 = row0 + (size_t)(warp_m * 32 + mt * 16 + g);
        size_t r1 = r0 + 8;
        #pragma unroll
        for (int nt = 0; nt < 8; nt++) {
            int cb = warp_n * 64 + nt * 8 + q * 2;
            float bz0 = __ldg(&bias[cb]), bz1 = __ldg(&bias[cb + 1]);
            float v00 = acc[mt][nt][0] + bz0, v01 = acc[mt][nt][1] + bz1;
            float v10 = acc[mt][nt][2] + bz0, v11 = acc[mt][nt][3] + bz1;
            if (final_layer) {
                if (r0 < NN) {
                    hout32[r0 * DD + cb]     = v00;
                    hout32[r0 * DD + cb + 1] = v01;
                }
                if (r1 < NN) {
                    hout32[r1 * DD + cb]     = v10;
                    hout32[r1 * DD + cb + 1] = v11;
                }
            } else {
                if (r0 < NN)
                    *reinterpret_cast<__half2*>(hout16 + r0 * DD + cb) = __floats2half2_rn(v00, v01);
                if (r1 < NN)
                    *reinterpret_cast<__half2*>(hout16 + r1 * DD + cb) = __floats2half2_rn(v10, v11);
            }
        }
    }
}

// ---------------- launch ----------------
extern "C" void kernel_launch(void* const* d_in, const int* in_sizes, int n_in,
                              void* d_out, int out_size) {
    const float* feat = (const float*)d_in[0];
    const float* W    = (const float*)d_in[1];
    const float* Ws   = (const float*)d_in[2];
    const float* bias = (const float*)d_in[3];
    const int*   src  = (const int*)d_in[4];
    const int*   dst  = (const int*)d_in[5];
    const int*   ety  = (const int*)d_in[6];
    float*       out  = (float*)d_out;

    static int smem_set = 0;
    if (!smem_set) {
        cudaFuncSetAttribute(k_gemm, cudaFuncAttributeMaxDynamicSharedMemorySize, GEMM_SMEM);
        smem_set = 1;
    }

    void* hsym = nullptr;
    cudaGetSymbolAddress(&hsym, g_h16);
    __half* h0 = (__half*)hsym;
    __half* h1 = h0 + (size_t)NN * DD;
    void* hfsym = nullptr;
    cudaGetSymbolAddress(&hfsym, g_hf16);
    __half* hf = (__half*)hfsym;
    void* degsym = nullptr;
    cudaGetSymbolAddress(&degsym, g_deg);

    // CSR by dst (graph fixed across layers -> build once per launch)
    cudaMemsetAsync(degsym, 0, (size_t)NN * sizeof(int));
    k_pre<<<(int)((WT_ITEMS + (size_t)FH_ITEMS + 255) / 256), 256>>>(W, Ws, feat, dst);
    k_scan1<<<98, 1024>>>();
    k_scan3<<<98, 1024>>>();           // block-sum scan fused in
    k_scatter<<<(NE + 255) / 256, 256>>>(src, dst, ety);

    const __half* hin = hf;
    for (int l = 0; l < LL; l++) {
        k_agg<<<(NN * 32 + 255) / 256, 256>>>((const uint2*)hin);
        __half* ho16 = (l == 0) ? h0 : h1;
        k_gemm<<<NTILE, 256, GEMM_SMEM>>>(l, bias + l * DD, ho16, out, (l == 2) ? 1 : 0);
        hin = ho16;
    }
}